// round 10
// baseline (speedup 1.0000x reference)
#include <cuda_runtime.h>
#include <math.h>

// ---------------- problem constants ----------------
#define N_SAMP  441000
#define ROWS    16
#define WPR16   27563          // ceil(441000/16); last window has 8 valid samples
#define FULLW   27562
#define CHUNKS  320
#define CW      88             // windows per chunk
#define TWPR    (CW * CHUNKS)  // 28160 transposed slots per row
#define EPR     TWPR
#define WARM_W  616            // warmup windows = 9856 samples (7 chunks)

// exp(-1/441), exp(-1/4410)
#define A_AT_D  0.99773499530690318
#define A_REL_D 0.99977326833789451
#define C_DB    6.0205999132796239f   // 20*log10(y) = C_DB * log2(y)

__host__ __device__ constexpr double slope16(int m) {
    double r = 1.0;
    for (int i = 0; i < m; ++i) r *= A_AT_D;
    for (int i = m; i < 16; ++i) r *= A_REL_D;
    return r;
}
#define SC(m) ((float)slope16(m))

// ---------------- gain LUT config ----------------
#define LUT_N         8192
#define LUT_LO_D      (-81.0)
#define LUT_HI_D      (61.0)
#define LUT_STEP_D    ((LUT_HI_D - LUT_LO_D) / (double)LUT_N)
#define LUT_LO_F      ((float)LUT_LO_D)
#define LUT_INVSTEP_F ((float)(1.0 / LUT_STEP_D))

// ---------------- packed f32x2 helpers ----------------
#define FFMA2_(d, a, b, c) \
    asm("fma.rn.f32x2 %0, %1, %2, %3;" : "=l"(d) : "l"(a), "l"(b), "l"(c))
#define PACKF2(d, lo, hi) \
    asm("mov.b64 %0, {%1, %2};" : "=l"(d) : "f"(lo), "f"(hi))
#define UNPACKF2(lo, hi, d) \
    asm("mov.b64 {%0, %1}, %2;" : "=f"(lo), "=f"(hi) : "l"(d))

// ---------------- scratch (static device globals) ----------------
static __device__ float4 g_p0[ROWS * TWPR];   // planes D[0..3]   (transposed)
static __device__ float4 g_p1[ROWS * TWPR];   // planes D[4..7]
static __device__ float4 g_p2[ROWS * TWPR];   // planes D[8..11]
static __device__ float4 g_p3[ROWS * TWPR];   // planes D[12..15]
static __device__ float  g_p4[ROWS * TWPR];   // plane D[16], grouped 4-per-f4
static __device__ float  g_entry[ROWS * EPR];
static __device__ float2 g_lut[LUT_N];        // (m, m_next - m)

// ---------------- LUT builder ----------------
__device__ double lut_gain_db(double dd) {
    double gdn = 0.0;
    if (dd > -0.1) {
        double t = dd - 0.1;
        gdn = -0.49250374812593705 * (dd + 0.1 + sqrt(t * t + 1e-4));
    }
    double du = -dd;
    double gup = 0.0;
    if (du > -0.1) {
        double t = du - 0.1;
        gup = 0.45 * (du + 0.1 + sqrt(t * t + 1e-4));
        if (gup > 36.0) gup = 36.0;
    }
    return gdn + gup;
}

// ---------------- kernel 1: prepass (x -> 17 transposed planes) -----------
__global__ void __launch_bounds__(CHUNKS) k_prepass(const float* __restrict__ x) {
    int q   = threadIdx.x;          // 0..319 (chunk id)
    int k   = blockIdx.x;           // 0..87  (window within chunk)
    int row = blockIdx.y;

    if (row == 0 && k < 26) {       // fold LUT build in
        int i = k * CHUNKS + q;
        if (i < LUT_N) {
            double d0 = LUT_LO_D + i * LUT_STEP_D;
            double m0 = pow(10.0, lut_gain_db(d0) / 20.0);
            double m1 = m0;
            if (i + 1 < LUT_N) {
                double d1 = LUT_LO_D + (i + 1) * LUT_STEP_D;
                m1 = pow(10.0, lut_gain_db(d1) / 20.0);
            }
            g_lut[i] = make_float2((float)m0, (float)(m1 - m0));
        }
    }

    int w = q * CW + k;             // global 16-window index in row
    const float* xr = x + row * N_SAMP;
    float v[16];
    if (w < FULLW) {
        const float4* x4 = (const float4*)(xr + w * 16);
        float4 a = x4[0], b = x4[1], c = x4[2], d = x4[3];
        v[0]=a.x; v[1]=a.y; v[2]=a.z; v[3]=a.w;
        v[4]=b.x; v[5]=b.y; v[6]=b.z; v[7]=b.w;
        v[8]=c.x; v[9]=c.y; v[10]=c.z; v[11]=c.w;
        v[12]=d.x; v[13]=d.y; v[14]=d.z; v[15]=d.w;
    } else {
        int base = w * 16;
#pragma unroll
        for (int i = 0; i < 16; ++i)
            v[i] = (base + i < N_SAMP) ? xr[base + i] : 0.0f;
    }
#pragma unroll
    for (int i = 0; i < 16; ++i)
        v[i] = C_DB * __log2f(fabsf(v[i]) + 1e-8f);

    const float AT = (float)A_AT_D, RL = (float)A_REL_D;
    const float BT = 1.0f - AT, BR = 1.0f - RL;

    float D[17];
    D[0] = BR * v[0];
    D[1] = BT * v[0];
#pragma unroll
    for (int t = 1; t < 16; ++t) {
        float bt = BT * v[t], br = BR * v[t];
        D[t + 1] = fmaf(AT, D[t], bt);
#pragma unroll
        for (int m = 15; m >= 1; --m) {
            if (m <= t)
                D[m] = fmaxf(fmaf(AT, D[m - 1], bt), fmaf(RL, D[m], br));
        }
        D[0] = fmaf(RL, D[0], br);
    }

    int idx = row * TWPR + k * CHUNKS + q;   // transposed slot (coalesced)
    g_p0[idx] = make_float4(D[0],  D[1],  D[2],  D[3]);
    g_p1[idx] = make_float4(D[4],  D[5],  D[6],  D[7]);
    g_p2[idx] = make_float4(D[8],  D[9],  D[10], D[11]);
    g_p3[idx] = make_float4(D[12], D[13], D[14], D[15]);
    g_p4[row * TWPR + ((k >> 2) * CHUNKS + q) * 4 + (k & 3)] = D[16];
}

// ---------------- kernel 2: dual-chain chunked scan -----------------------
#define STEPX(S, j, c4v)                                                      \
    {                                                                         \
        unsigned long long s2, r0, r1, r2, r3, r4, r5, r6, r7;                \
        PACKF2(s2, s##S, s##S);                                               \
        FFMA2_(r0, s2, K01, U0##S[j].x); FFMA2_(r1, s2, K23, U0##S[j].y);     \
        FFMA2_(r2, s2, K45, U1##S[j].x); FFMA2_(r3, s2, K67, U1##S[j].y);     \
        FFMA2_(r4, s2, K89, U2##S[j].x); FFMA2_(r5, s2, KAB, U2##S[j].y);     \
        FFMA2_(r6, s2, KCD, U3##S[j].x); FFMA2_(r7, s2, KEF, U3##S[j].y);     \
        float q16 = fmaf(SC(16), s##S, c4v);                                  \
        float e0, e1, t0, t1, t2, t3, t4, t5, t6, t7;                         \
        UNPACKF2(e0, e1, r0); t0 = fmaxf(e0, e1);                             \
        UNPACKF2(e0, e1, r1); t1 = fmaxf(e0, e1);                             \
        UNPACKF2(e0, e1, r2); t2 = fmaxf(e0, e1);                             \
        UNPACKF2(e0, e1, r3); t3 = fmaxf(e0, e1);                             \
        UNPACKF2(e0, e1, r4); t4 = fmaxf(e0, e1);                             \
        UNPACKF2(e0, e1, r5); t5 = fmaxf(e0, e1);                             \
        UNPACKF2(e0, e1, r6); t6 = fmaxf(e0, e1);                             \
        UNPACKF2(e0, e1, r7); t7 = fmaxf(e0, e1);                             \
        float u0 = fmaxf(t0, t1), u1 = fmaxf(t2, t3);                         \
        float u2 = fmaxf(t4, t5), u3 = fmaxf(t6, t7);                         \
        s##S = fmaxf(fmaxf(fmaxf(u0, u1), fmaxf(u2, u3)), q16);               \
    }

#define RF(S, j)                                                              \
    {                                                                         \
        U0##S[j] = pf0##S[(j) * CHUNKS]; U1##S[j] = pf1##S[(j) * CHUNKS];     \
        U2##S[j] = pf2##S[(j) * CHUNKS]; U3##S[j] = pf3##S[(j) * CHUNKS];     \
    }

#define ADV(S)                                                                \
    {                                                                         \
        fk##S += 4;                                                           \
        if (fk##S == CW) {                                                    \
            fk##S = 0; ++fq##S;                                               \
            pf0##S = b0 + fq##S; pf1##S = b1 + fq##S;                         \
            pf2##S = b2 + fq##S; pf3##S = b3 + fq##S; pf4##S = b4 + fq##S;    \
        } else {                                                              \
            pf0##S += 4 * CHUNKS; pf1##S += 4 * CHUNKS;                       \
            pf2##S += 4 * CHUNKS; pf3##S += 4 * CHUNKS;                       \
            pf4##S += CHUNKS;                                                 \
        }                                                                     \
    }

#define BLOCK4(S)                                                             \
    {                                                                         \
        float4 CCn = pf4##S[0];                                               \
        STEPX(S, 0, CCc##S.x); RF(S, 0);                                      \
        STEPX(S, 1, CCc##S.y); RF(S, 1);                                      \
        STEPX(S, 2, CCc##S.z); RF(S, 2);                                      \
        STEPX(S, 3, CCc##S.w); RF(S, 3);                                      \
        CCc##S = CCn;                                                         \
        ADV(S);                                                               \
    }

#define BLOCK4_ST(S, en, it)                                                  \
    {                                                                         \
        float4 CCn = pf4##S[0];                                               \
        float w0 = s##S; STEPX(S, 0, CCc##S.x); RF(S, 0);                     \
        float w1 = s##S; STEPX(S, 1, CCc##S.y); RF(S, 1);                     \
        float w2 = s##S; STEPX(S, 2, CCc##S.z); RF(S, 2);                     \
        float w3 = s##S; STEPX(S, 3, CCc##S.w); RF(S, 3);                     \
        CCc##S = CCn;                                                         \
        ADV(S);                                                               \
        *(float4*)((en) + (it) * 4) = make_float4(w0, w1, w2, w3);            \
    }

#define CHAIN_INIT(S, qv)                                                     \
    int fq##S = max(0, (qv) - 7);                                             \
    int fk##S = 0;                                                            \
    const ulonglong2 *pf0##S = b0 + fq##S, *pf1##S = b1 + fq##S,              \
                     *pf2##S = b2 + fq##S, *pf3##S = b3 + fq##S;              \
    const float4* pf4##S = b4 + fq##S;                                        \
    ulonglong2 U0##S[4], U1##S[4], U2##S[4], U3##S[4];                        \
    _Pragma("unroll")                                                         \
    for (int j = 0; j < 4; ++j) { RF(S, j); }                                 \
    float4 CCc##S = pf4##S[0];                                                \
    ADV(S);                                                                   \
    float s##S;

__global__ void __launch_bounds__(32) k_scan(const float* __restrict__ x) {
    int blk = blockIdx.x;            // 0..79
    int row = blk / 5;
    int g   = blk % 5;
    int i   = threadIdx.x;
    int qa  = g * 64 + i;            // chain A chunk
    int qb  = qa + 32;               // chain B chunk (always >= 32)

    const ulonglong2* b0 = (const ulonglong2*)(g_p0 + row * TWPR);
    const ulonglong2* b1 = (const ulonglong2*)(g_p1 + row * TWPR);
    const ulonglong2* b2 = (const ulonglong2*)(g_p2 + row * TWPR);
    const ulonglong2* b3 = (const ulonglong2*)(g_p3 + row * TWPR);
    const float4*     b4 = (const float4*)g_p4 + row * (TWPR / 4);

    unsigned long long K01, K23, K45, K67, K89, KAB, KCD, KEF;
    PACKF2(K01, SC(0),  SC(1));  PACKF2(K23, SC(2),  SC(3));
    PACKF2(K45, SC(4),  SC(5));  PACKF2(K67, SC(6),  SC(7));
    PACKF2(K89, SC(8),  SC(9));  PACKF2(KAB, SC(10), SC(11));
    PACKF2(KCD, SC(12), SC(13)); PACKF2(KEF, SC(14), SC(15));

    CHAIN_INIT(A, qa)
    CHAIN_INIT(B, qb)

    const float SEST = (float)(1.0 / (1.0 - slope16(16)));
    // Chain A: chunks 0..7 warm up from window 0 -> use the reference's EXACT
    // initial state rect_db[row][0] (zero seed error, exact prefix replay).
    // Otherwise: fixed point of all-attack plane, biased 25 dB low, with a
    // full 616-window warmup (recovers at the fast attack rate).
    sA = (qa <= 7) ? (C_DB * __log2f(fabsf(x[row * N_SAMP]) + 1e-8f))
                   : fmaf(CCcA.x, SEST, -25.0f);
    sB = fmaf(CCcB.x, SEST, -25.0f);   // qb >= 32: always full warmup

    // warmup: 154 blocks of 4 windows (616 windows); chain A skips the
    // first skipA blocks when its chunk is near the row start.
    int skipA = (7 - min(qa, 7)) * 22;
    for (int it = 0; it < WARM_W / 4; ++it) {
        if (it >= skipA) { BLOCK4(A) }
        BLOCK4(B)
    }

    // active: 22 blocks, store entry states
    float* enA = g_entry + row * EPR + qa * CW;
    float* enB = g_entry + row * EPR + qb * CW;
    for (int it = 0; it < CW / 4; ++it) {
        BLOCK4_ST(A, enA, it)
        BLOCK4_ST(B, enB, it)
    }
}

// ---------------- kernel 3: expand + LUT epilogue -------------------------
__global__ void __launch_bounds__(256) k_expand(const float* __restrict__ x,
                                                const float* __restrict__ thr,
                                                const float* __restrict__ dep,
                                                float* __restrict__ out) {
    int wi = blockIdx.x * 256 + threadIdx.x;
    if (wi >= WPR16) return;
    int row = blockIdx.y;

    float tdb = fmaf(thr[row], 40.0f, -40.0f);
    float dpv = dep[row];
    bool  d1  = (dpv == 1.0f);
    float off = (-tdb - LUT_LO_F) * LUT_INVSTEP_F;

    const float AT = (float)A_AT_D, RL = (float)A_REL_D;
    const float BT = 1.0f - AT, BR = 1.0f - RL;

    float s = g_entry[row * EPR + wi];

    const float* xr = x + row * N_SAMP;
    float* outr = out + row * N_SAMP;
    int base = wi * 16;
    int nval = (wi < FULLW) ? 16 : (N_SAMP - base);

    float xi[16];
    if (nval == 16) {
        const float4* x4 = (const float4*)(xr + base);
        float4 a = x4[0], b = x4[1], c = x4[2], d = x4[3];
        xi[0]=a.x; xi[1]=a.y; xi[2]=a.z; xi[3]=a.w;
        xi[4]=b.x; xi[5]=b.y; xi[6]=b.z; xi[7]=b.w;
        xi[8]=c.x; xi[9]=c.y; xi[10]=c.z; xi[11]=c.w;
        xi[12]=d.x; xi[13]=d.y; xi[14]=d.z; xi[15]=d.w;
    } else {
#pragma unroll
        for (int i = 0; i < 16; ++i)
            xi[i] = (i < nval) ? xr[base + i] : 0.0f;
    }

    float o[16];
#pragma unroll
    for (int i = 0; i < 16; ++i) {
        float v = C_DB * __log2f(fabsf(xi[i]) + 1e-8f);
        s = fmaxf(fmaf(AT, s, BT * v), fmaf(RL, s, BR * v));

        float fi = fmaf(s, LUT_INVSTEP_F, off);
        fi = fminf(fmaxf(fi, 0.0f), (float)(LUT_N - 2) + 0.999f);
        int   ii = (int)fi;
        float fr = fi - (float)ii;
        float2 e = g_lut[ii];
        float m = fmaf(fr, e.y, e.x);
        if (!d1) m = exp2f(__log2f(m) * dpv);
        o[i] = xi[i] * m;
    }

    if (nval == 16) {
        float4* o4 = (float4*)(outr + base);
        o4[0] = make_float4(o[0],  o[1],  o[2],  o[3]);
        o4[1] = make_float4(o[4],  o[5],  o[6],  o[7]);
        o4[2] = make_float4(o[8],  o[9],  o[10], o[11]);
        o4[3] = make_float4(o[12], o[13], o[14], o[15]);
    } else {
#pragma unroll
        for (int i = 0; i < 16; ++i)
            if (i < nval) outr[base + i] = o[i];
    }
}

// ---------------- entry point (single stream, no allocations) -------------
extern "C" void kernel_launch(void* const* d_in, const int* in_sizes, int n_in,
                              void* d_out, int out_size) {
    const float* x   = (const float*)d_in[0];
    const float* thr = (const float*)d_in[1];
    const float* dep = (const float*)d_in[2];
    float* out = (float*)d_out;

    k_prepass<<<dim3(CW, ROWS), CHUNKS>>>(x);
    k_scan<<<ROWS * 5, 32>>>(x);
    k_expand<<<dim3((WPR16 + 255) / 256, ROWS), 256>>>(x, thr, dep, out);
}

// round 11
// speedup vs baseline: 1.8346x; 1.8346x over previous
#include <cuda_runtime.h>
#include <math.h>

// ---------------- problem constants ----------------
#define N_SAMP  441000
#define ROWS    16
#define WPR16   27563          // ceil(441000/16); last window has 8 valid samples
#define FULLW   27562
#define CHUNKS  320
#define CW      88             // windows per chunk
#define TWPR    (CW * CHUNKS)  // 28160 transposed slots per row
#define EPR     TWPR
#define WARM_W  616            // warmup windows = 9856 samples (7 chunks)
#define PD      8              // U-ring prefetch depth

// exp(-1/441), exp(-1/4410)
#define A_AT_D  0.99773499530690318
#define A_REL_D 0.99977326833789451
#define C_DB    6.0205999132796239f   // 20*log10(y) = C_DB * log2(y)

__host__ __device__ constexpr double slope16(int m) {
    double r = 1.0;
    for (int i = 0; i < m; ++i) r *= A_AT_D;
    for (int i = m; i < 16; ++i) r *= A_REL_D;
    return r;
}
#define SC(m) ((float)slope16(m))

// ---------------- gain LUT config ----------------
#define LUT_N         8192
#define LUT_LO_D      (-81.0)
#define LUT_HI_D      (61.0)
#define LUT_STEP_D    ((LUT_HI_D - LUT_LO_D) / (double)LUT_N)
#define LUT_LO_F      ((float)LUT_LO_D)
#define LUT_INVSTEP_F ((float)(1.0 / LUT_STEP_D))

// ---------------- packed f32x2 helpers ----------------
#define FFMA2_(d, a, b, c) \
    asm("fma.rn.f32x2 %0, %1, %2, %3;" : "=l"(d) : "l"(a), "l"(b), "l"(c))
#define PACKF2(d, lo, hi) \
    asm("mov.b64 %0, {%1, %2};" : "=l"(d) : "f"(lo), "f"(hi))
#define UNPACKF2(lo, hi, d) \
    asm("mov.b64 {%0, %1}, %2;" : "=f"(lo), "=f"(hi) : "l"(d))

// ---------------- scratch (static device globals) ----------------
static __device__ float4 g_p0[ROWS * TWPR];   // planes D[0..3]   (transposed)
static __device__ float4 g_p1[ROWS * TWPR];   // planes D[4..7]
static __device__ float4 g_p2[ROWS * TWPR];   // planes D[8..11]
static __device__ float4 g_p3[ROWS * TWPR];   // planes D[12..15]
static __device__ float  g_p4[ROWS * TWPR];   // plane D[16], grouped 4-per-f4
static __device__ float  g_entry[ROWS * EPR];
static __device__ float2 g_lut[LUT_N];        // (m, m_next - m)

// ---------------- LUT builder ----------------
__device__ double lut_gain_db(double dd) {
    double gdn = 0.0;
    if (dd > -0.1) {
        double t = dd - 0.1;
        gdn = -0.49250374812593705 * (dd + 0.1 + sqrt(t * t + 1e-4));
    }
    double du = -dd;
    double gup = 0.0;
    if (du > -0.1) {
        double t = du - 0.1;
        gup = 0.45 * (du + 0.1 + sqrt(t * t + 1e-4));
        if (gup > 36.0) gup = 36.0;
    }
    return gdn + gup;
}

// ---------------- per-window DP (prepass helper) ----------------
__device__ __forceinline__ void dp_window(const float* __restrict__ xr,
                                          int w, int row, int q, int k) {
    float v[16];
    if (w < FULLW) {
        const float4* x4 = (const float4*)(xr + w * 16);
        float4 a = x4[0], b = x4[1], c = x4[2], d = x4[3];
        v[0]=a.x; v[1]=a.y; v[2]=a.z; v[3]=a.w;
        v[4]=b.x; v[5]=b.y; v[6]=b.z; v[7]=b.w;
        v[8]=c.x; v[9]=c.y; v[10]=c.z; v[11]=c.w;
        v[12]=d.x; v[13]=d.y; v[14]=d.z; v[15]=d.w;
    } else {
        int base = w * 16;
#pragma unroll
        for (int i = 0; i < 16; ++i)
            v[i] = (base + i < N_SAMP) ? xr[base + i] : 0.0f;
    }
#pragma unroll
    for (int i = 0; i < 16; ++i)
        v[i] = C_DB * __log2f(fabsf(v[i]) + 1e-8f);

    const float AT = (float)A_AT_D, RL = (float)A_REL_D;
    const float BT = 1.0f - AT, BR = 1.0f - RL;

    // DP over attack-count m: D[m] = max offset among paths with m attacks
    float D[17];
    D[0] = BR * v[0];
    D[1] = BT * v[0];
#pragma unroll
    for (int t = 1; t < 16; ++t) {
        float bt = BT * v[t], br = BR * v[t];
        D[t + 1] = fmaf(AT, D[t], bt);
#pragma unroll
        for (int m = 15; m >= 1; --m) {
            if (m <= t)
                D[m] = fmaxf(fmaf(AT, D[m - 1], bt), fmaf(RL, D[m], br));
        }
        D[0] = fmaf(RL, D[0], br);
    }

    int idx = row * TWPR + k * CHUNKS + q;   // transposed slot (coalesced)
    g_p0[idx] = make_float4(D[0],  D[1],  D[2],  D[3]);
    g_p1[idx] = make_float4(D[4],  D[5],  D[6],  D[7]);
    g_p2[idx] = make_float4(D[8],  D[9],  D[10], D[11]);
    g_p3[idx] = make_float4(D[12], D[13], D[14], D[15]);
    g_p4[row * TWPR + ((k >> 2) * CHUNKS + q) * 4 + (k & 3)] = D[16];
}

// ---------------- kernel 1: prepass (pair of windows per thread) ----------
// grid (CW/2, ROWS), block CHUNKS. thread q = chunk id, block.x = j -> k=2j,2j+1.
// Single wave (225k threads); window 2j+1's x line is an L1 hit.
__global__ void __launch_bounds__(CHUNKS) k_prepass(const float* __restrict__ x) {
    int q   = threadIdx.x;          // 0..319 (chunk id)
    int j   = blockIdx.x;           // 0..43
    int row = blockIdx.y;

    if (row == 0 && j < 26) {       // fold LUT build in
        int i = j * CHUNKS + q;
        if (i < LUT_N) {
            double d0 = LUT_LO_D + i * LUT_STEP_D;
            double m0 = pow(10.0, lut_gain_db(d0) / 20.0);
            double m1 = m0;
            if (i + 1 < LUT_N) {
                double d1 = LUT_LO_D + (i + 1) * LUT_STEP_D;
                m1 = pow(10.0, lut_gain_db(d1) / 20.0);
            }
            g_lut[i] = make_float2((float)m0, (float)(m1 - m0));
        }
    }

    const float* xr = x + row * N_SAMP;
    int k0 = 2 * j;
    dp_window(xr, q * CW + k0,     row, q, k0);
    dp_window(xr, q * CW + k0 + 1, row, q, k0 + 1);
}

// ---------------- kernel 2: chunked scan (single chain, R6 math) ----------
#define STEP(j, c4v)                                                          \
    {                                                                         \
        unsigned long long s2, r0, r1, r2, r3, r4, r5, r6, r7;                \
        PACKF2(s2, s, s);                                                     \
        FFMA2_(r0, s2, K01, U0[j].x); FFMA2_(r1, s2, K23, U0[j].y);           \
        FFMA2_(r2, s2, K45, U1[j].x); FFMA2_(r3, s2, K67, U1[j].y);           \
        FFMA2_(r4, s2, K89, U2[j].x); FFMA2_(r5, s2, KAB, U2[j].y);           \
        FFMA2_(r6, s2, KCD, U3[j].x); FFMA2_(r7, s2, KEF, U3[j].y);           \
        float q16 = fmaf(SC(16), s, c4v);                                     \
        float e0, e1, t0, t1, t2, t3, t4, t5, t6, t7;                         \
        UNPACKF2(e0, e1, r0); t0 = fmaxf(e0, e1);                             \
        UNPACKF2(e0, e1, r1); t1 = fmaxf(e0, e1);                             \
        UNPACKF2(e0, e1, r2); t2 = fmaxf(e0, e1);                             \
        UNPACKF2(e0, e1, r3); t3 = fmaxf(e0, e1);                             \
        UNPACKF2(e0, e1, r4); t4 = fmaxf(e0, e1);                             \
        UNPACKF2(e0, e1, r5); t5 = fmaxf(e0, e1);                             \
        UNPACKF2(e0, e1, r6); t6 = fmaxf(e0, e1);                             \
        UNPACKF2(e0, e1, r7); t7 = fmaxf(e0, e1);                             \
        float u0 = fmaxf(t0, t1), u1 = fmaxf(t2, t3);                         \
        float u2 = fmaxf(t4, t5), u3 = fmaxf(t6, t7);                         \
        s = fmaxf(fmaxf(fmaxf(u0, u1), fmaxf(u2, u3)), q16);                  \
    }

#define RF(j)                                                                 \
    {                                                                         \
        U0[j] = pf0[(j) * CHUNKS]; U1[j] = pf1[(j) * CHUNKS];                 \
        U2[j] = pf2[(j) * CHUNKS]; U3[j] = pf3[(j) * CHUNKS];                 \
    }

#define ADVANCE()                                                             \
    {                                                                         \
        fk += PD;                                                             \
        if (fk == CW) {                                                       \
            fk = 0; ++fq;                                                     \
            pf0 = b0 + fq; pf1 = b1 + fq; pf2 = b2 + fq;                      \
            pf3 = b3 + fq; pf4 = b4 + fq;                                     \
        } else {                                                              \
            pf0 += PD * CHUNKS; pf1 += PD * CHUNKS;                           \
            pf2 += PD * CHUNKS; pf3 += PD * CHUNKS;                           \
            pf4 += 2 * CHUNKS;                                                \
        }                                                                     \
    }

// Invariant entering each BLOCK8: pf* point at the NEXT block; CCa/CCb hold
// the CURRENT block's plane-16 pair. Next pair is fetched at block START
// (8-15 window distance -> L2 latency fully covered).
#define BLOCK8()                                                              \
    {                                                                         \
        float4 CAn = pf4[0];                                                  \
        float4 CBn = pf4[CHUNKS];                                             \
        STEP(0, CCa.x); RF(0); STEP(1, CCa.y); RF(1);                         \
        STEP(2, CCa.z); RF(2); STEP(3, CCa.w); RF(3);                         \
        STEP(4, CCb.x); RF(4); STEP(5, CCb.y); RF(5);                         \
        STEP(6, CCb.z); RF(6); STEP(7, CCb.w); RF(7);                         \
        CCa = CAn; CCb = CBn;                                                 \
        ADVANCE();                                                            \
    }

#define BLOCK8_ST(en, it)                                                     \
    {                                                                         \
        float4 CAn = pf4[0];                                                  \
        float4 CBn = pf4[CHUNKS];                                             \
        float ss0 = s; STEP(0, CCa.x); RF(0);                                 \
        float ss1 = s; STEP(1, CCa.y); RF(1);                                 \
        float ss2 = s; STEP(2, CCa.z); RF(2);                                 \
        float ss3 = s; STEP(3, CCa.w); RF(3);                                 \
        float ss4 = s; STEP(4, CCb.x); RF(4);                                 \
        float ss5 = s; STEP(5, CCb.y); RF(5);                                 \
        float ss6 = s; STEP(6, CCb.z); RF(6);                                 \
        float ss7 = s; STEP(7, CCb.w); RF(7);                                 \
        CCa = CAn; CCb = CBn;                                                 \
        ADVANCE();                                                            \
        float4* e4 = (float4*)((en) + (it) * PD);                             \
        e4[0] = make_float4(ss0, ss1, ss2, ss3);                              \
        e4[1] = make_float4(ss4, ss5, ss6, ss7);                              \
    }

__global__ void __launch_bounds__(32) k_scan(const float* __restrict__ x) {
    int gid = blockIdx.x * 32 + threadIdx.x;   // 0..5119
    int row = gid / CHUNKS;
    int c   = gid % CHUNKS;
    int start_w = c * CW;
    int warm_w  = max(0, start_w - WARM_W);    // multiple of CW

    const ulonglong2* b0 = (const ulonglong2*)(g_p0 + row * TWPR);
    const ulonglong2* b1 = (const ulonglong2*)(g_p1 + row * TWPR);
    const ulonglong2* b2 = (const ulonglong2*)(g_p2 + row * TWPR);
    const ulonglong2* b3 = (const ulonglong2*)(g_p3 + row * TWPR);
    const float4*     b4 = (const float4*)g_p4 + row * (TWPR / 4);

    int fq = warm_w / CW;
    int fk = 0;
    const ulonglong2* pf0 = b0 + fq;
    const ulonglong2* pf1 = b1 + fq;
    const ulonglong2* pf2 = b2 + fq;
    const ulonglong2* pf3 = b3 + fq;
    const float4*     pf4 = b4 + fq;

    unsigned long long K01, K23, K45, K67, K89, KAB, KCD, KEF;
    PACKF2(K01, SC(0),  SC(1));  PACKF2(K23, SC(2),  SC(3));
    PACKF2(K45, SC(4),  SC(5));  PACKF2(K67, SC(6),  SC(7));
    PACKF2(K89, SC(8),  SC(9));  PACKF2(KAB, SC(10), SC(11));
    PACKF2(KCD, SC(12), SC(13)); PACKF2(KEF, SC(14), SC(15));

    ulonglong2 U0[PD], U1[PD], U2[PD], U3[PD];
#pragma unroll
    for (int j = 0; j < PD; ++j) RF(j);
    float4 CCa = pf4[0];
    float4 CCb = pf4[CHUNKS];

    float s;
    if (warm_w == 0) {
        // exact init: reference seeds with rect_db[row][0]
        s = C_DB * __log2f(fabsf(x[row * N_SAMP]) + 1e-8f);
    } else {
        // seed: fixed point of all-attack plane, biased 25 dB low so
        // recovery runs at the fast attack rate
        const float SEST = (float)(1.0 / (1.0 - slope16(16)));
        s = fmaf(CCa.x, SEST, -25.0f);
    }

    ADVANCE();   // pf* now point at block 1 (invariant for BLOCK8)

    // ---- warmup (no stores) ----
    int nwb = (start_w - warm_w) >> 3;
    for (int i = 0; i < nwb; ++i) BLOCK8();

    // ---- active: CW/PD = 11 blocks, store entry states ----
    float* en = g_entry + row * EPR + start_w;
    for (int i = 0; i < CW / PD; ++i) BLOCK8_ST(en, i);
}

// ---------------- kernel 3: expand + LUT epilogue -------------------------
__global__ void __launch_bounds__(256) k_expand(const float* __restrict__ x,
                                                const float* __restrict__ thr,
                                                const float* __restrict__ dep,
                                                float* __restrict__ out) {
    int wi = blockIdx.x * 256 + threadIdx.x;
    if (wi >= WPR16) return;
    int row = blockIdx.y;

    float tdb = fmaf(thr[row], 40.0f, -40.0f);
    float dpv = dep[row];
    bool  d1  = (dpv == 1.0f);
    float off = (-tdb - LUT_LO_F) * LUT_INVSTEP_F;

    const float AT = (float)A_AT_D, RL = (float)A_REL_D;
    const float BT = 1.0f - AT, BR = 1.0f - RL;

    float s = g_entry[row * EPR + wi];

    const float* xr = x + row * N_SAMP;
    float* outr = out + row * N_SAMP;
    int base = wi * 16;
    int nval = (wi < FULLW) ? 16 : (N_SAMP - base);

    float xi[16];
    if (nval == 16) {
        const float4* x4 = (const float4*)(xr + base);
        float4 a = x4[0], b = x4[1], c = x4[2], d = x4[3];
        xi[0]=a.x; xi[1]=a.y; xi[2]=a.z; xi[3]=a.w;
        xi[4]=b.x; xi[5]=b.y; xi[6]=b.z; xi[7]=b.w;
        xi[8]=c.x; xi[9]=c.y; xi[10]=c.z; xi[11]=c.w;
        xi[12]=d.x; xi[13]=d.y; xi[14]=d.z; xi[15]=d.w;
    } else {
#pragma unroll
        for (int i = 0; i < 16; ++i)
            xi[i] = (i < nval) ? xr[base + i] : 0.0f;
    }

    float o[16];
#pragma unroll
    for (int i = 0; i < 16; ++i) {
        float v = C_DB * __log2f(fabsf(xi[i]) + 1e-8f);
        s = fmaxf(fmaf(AT, s, BT * v), fmaf(RL, s, BR * v));

        float fi = fmaf(s, LUT_INVSTEP_F, off);
        fi = fminf(fmaxf(fi, 0.0f), (float)(LUT_N - 2) + 0.999f);
        int   ii = (int)fi;
        float fr = fi - (float)ii;
        float2 e = g_lut[ii];
        float m = fmaf(fr, e.y, e.x);
        if (!d1) m = exp2f(__log2f(m) * dpv);
        o[i] = xi[i] * m;
    }

    if (nval == 16) {
        float4* o4 = (float4*)(outr + base);
        o4[0] = make_float4(o[0],  o[1],  o[2],  o[3]);
        o4[1] = make_float4(o[4],  o[5],  o[6],  o[7]);
        o4[2] = make_float4(o[8],  o[9],  o[10], o[11]);
        o4[3] = make_float4(o[12], o[13], o[14], o[15]);
    } else {
#pragma unroll
        for (int i = 0; i < 16; ++i)
            if (i < nval) outr[base + i] = o[i];
    }
}

// ---------------- entry point (single stream, no allocations) -------------
extern "C" void kernel_launch(void* const* d_in, const int* in_sizes, int n_in,
                              void* d_out, int out_size) {
    const float* x   = (const float*)d_in[0];
    const float* thr = (const float*)d_in[1];
    const float* dep = (const float*)d_in[2];
    float* out = (float*)d_out;

    k_prepass<<<dim3(CW / 2, ROWS), CHUNKS>>>(x);
    k_scan<<<(ROWS * CHUNKS) / 32, 32>>>(x);
    k_expand<<<dim3((WPR16 + 255) / 256, ROWS), 256>>>(x, thr, dep, out);
}

// round 13
// speedup vs baseline: 1.9625x; 1.0697x over previous
#include <cuda_runtime.h>
#include <math.h>

// ---------------- problem constants ----------------
#define N_SAMP  441000
#define ROWS    16
#define WPR16   27563          // ceil(441000/16); last window has 8 valid samples
#define FULLW   27562
#define CHUNKS  160
#define CW      176            // windows per chunk (176 % 8 == 0)
#define TWPR    (CW * CHUNKS)  // 28160 transposed slots per row
#define EPR     TWPR
#define WARM_W  616            // warmup windows = 9856 samples; % 8 == 0
#define PD      8              // U-ring prefetch depth

// exp(-1/441), exp(-1/4410)
#define A_AT_D  0.99773499530690318
#define A_REL_D 0.99977326833789451
#define C_DB    6.0205999132796239f   // 20*log10(y) = C_DB * log2(y)

__host__ __device__ constexpr double slope16(int m) {
    double r = 1.0;
    for (int i = 0; i < m; ++i) r *= A_AT_D;
    for (int i = m; i < 16; ++i) r *= A_REL_D;
    return r;
}
#define SC(m) ((float)slope16(m))

// ---------------- gain LUT config ----------------
#define LUT_N         8192
#define LUT_LO_D      (-81.0)
#define LUT_HI_D      (61.0)
#define LUT_STEP_D    ((LUT_HI_D - LUT_LO_D) / (double)LUT_N)
#define LUT_LO_F      ((float)LUT_LO_D)
#define LUT_INVSTEP_F ((float)(1.0 / LUT_STEP_D))

// ---------------- packed f32x2 helpers ----------------
#define FFMA2_(d, a, b, c) \
    asm("fma.rn.f32x2 %0, %1, %2, %3;" : "=l"(d) : "l"(a), "l"(b), "l"(c))
#define PACKF2(d, lo, hi) \
    asm("mov.b64 %0, {%1, %2};" : "=l"(d) : "f"(lo), "f"(hi))
#define UNPACKF2(lo, hi, d) \
    asm("mov.b64 {%0, %1}, %2;" : "=f"(lo), "=f"(hi) : "l"(d))

// ---------------- scratch (static device globals) ----------------
static __device__ float4 g_p0[ROWS * TWPR];   // planes D[0..3]   (transposed)
static __device__ float4 g_p1[ROWS * TWPR];   // planes D[4..7]
static __device__ float4 g_p2[ROWS * TWPR];   // planes D[8..11]
static __device__ float4 g_p3[ROWS * TWPR];   // planes D[12..15]
static __device__ float  g_p4[ROWS * TWPR];   // plane D[16], grouped 4-per-f4
static __device__ float  g_entry[ROWS * EPR];
static __device__ float2 g_lut[LUT_N];        // (m, m_next - m)

// ---------------- LUT builder ----------------
__device__ double lut_gain_db(double dd) {
    double gdn = 0.0;
    if (dd > -0.1) {
        double t = dd - 0.1;
        gdn = -0.49250374812593705 * (dd + 0.1 + sqrt(t * t + 1e-4));
    }
    double du = -dd;
    double gup = 0.0;
    if (du > -0.1) {
        double t = du - 0.1;
        gup = 0.45 * (du + 0.1 + sqrt(t * t + 1e-4));
        if (gup > 36.0) gup = 36.0;
    }
    return gdn + gup;
}

// ---------------- kernel 1: prepass (x -> 17 transposed planes) -----------
// grid (CW, ROWS), block CHUNKS. thread q = chunk id, block.x = k in chunk.
__global__ void __launch_bounds__(CHUNKS) k_prepass(const float* __restrict__ x) {
    int q   = threadIdx.x;          // 0..159 (chunk id)
    int k   = blockIdx.x;           // 0..175 (window within chunk)
    int row = blockIdx.y;

    if (row == 0 && k < 52) {       // fold LUT build in (52*160 >= 8192)
        int i = k * CHUNKS + q;
        if (i < LUT_N) {
            double d0 = LUT_LO_D + i * LUT_STEP_D;
            double m0 = pow(10.0, lut_gain_db(d0) / 20.0);
            double m1 = m0;
            if (i + 1 < LUT_N) {
                double d1 = LUT_LO_D + (i + 1) * LUT_STEP_D;
                m1 = pow(10.0, lut_gain_db(d1) / 20.0);
            }
            g_lut[i] = make_float2((float)m0, (float)(m1 - m0));
        }
    }

    int w = q * CW + k;             // global 16-window index in row
    const float* xr = x + row * N_SAMP;
    float v[16];
    if (w < FULLW) {
        const float4* x4 = (const float4*)(xr + w * 16);
        float4 a = x4[0], b = x4[1], c = x4[2], d = x4[3];
        v[0]=a.x; v[1]=a.y; v[2]=a.z; v[3]=a.w;
        v[4]=b.x; v[5]=b.y; v[6]=b.z; v[7]=b.w;
        v[8]=c.x; v[9]=c.y; v[10]=c.z; v[11]=c.w;
        v[12]=d.x; v[13]=d.y; v[14]=d.z; v[15]=d.w;
    } else {
        int base = w * 16;
#pragma unroll
        for (int i = 0; i < 16; ++i)
            v[i] = (base + i < N_SAMP) ? xr[base + i] : 0.0f;
    }
#pragma unroll
    for (int i = 0; i < 16; ++i)
        v[i] = C_DB * __log2f(fabsf(v[i]) + 1e-8f);

    const float AT = (float)A_AT_D, RL = (float)A_REL_D;
    const float BT = 1.0f - AT, BR = 1.0f - RL;

    // DP over attack-count m: D[m] = max offset among paths with m attacks
    float D[17];
    D[0] = BR * v[0];
    D[1] = BT * v[0];
#pragma unroll
    for (int t = 1; t < 16; ++t) {
        float bt = BT * v[t], br = BR * v[t];
        D[t + 1] = fmaf(AT, D[t], bt);
#pragma unroll
        for (int m = 15; m >= 1; --m) {
            if (m <= t)
                D[m] = fmaxf(fmaf(AT, D[m - 1], bt), fmaf(RL, D[m], br));
        }
        D[0] = fmaf(RL, D[0], br);
    }

    int idx = row * TWPR + k * CHUNKS + q;   // transposed slot (coalesced)
    g_p0[idx] = make_float4(D[0],  D[1],  D[2],  D[3]);
    g_p1[idx] = make_float4(D[4],  D[5],  D[6],  D[7]);
    g_p2[idx] = make_float4(D[8],  D[9],  D[10], D[11]);
    g_p3[idx] = make_float4(D[12], D[13], D[14], D[15]);
    g_p4[row * TWPR + ((k >> 2) * CHUNKS + q) * 4 + (k & 3)] = D[16];
}

// ---------------- kernel 2: chunked scan (scalar max tree) ----------------
#define STEP(j, c4v)                                                          \
    {                                                                         \
        unsigned long long s2, r0, r1, r2, r3, r4, r5, r6, r7;                \
        PACKF2(s2, s, s);                                                     \
        FFMA2_(r0, s2, K01, U0[j].x); FFMA2_(r1, s2, K23, U0[j].y);           \
        FFMA2_(r2, s2, K45, U1[j].x); FFMA2_(r3, s2, K67, U1[j].y);           \
        FFMA2_(r4, s2, K89, U2[j].x); FFMA2_(r5, s2, KAB, U2[j].y);           \
        FFMA2_(r6, s2, KCD, U3[j].x); FFMA2_(r7, s2, KEF, U3[j].y);           \
        float q16 = fmaf(SC(16), s, c4v);                                     \
        float e0, e1, t0, t1, t2, t3, t4, t5, t6, t7;                         \
        UNPACKF2(e0, e1, r0); t0 = fmaxf(e0, e1);                             \
        UNPACKF2(e0, e1, r1); t1 = fmaxf(e0, e1);                             \
        UNPACKF2(e0, e1, r2); t2 = fmaxf(e0, e1);                             \
        UNPACKF2(e0, e1, r3); t3 = fmaxf(e0, e1);                             \
        UNPACKF2(e0, e1, r4); t4 = fmaxf(e0, e1);                             \
        UNPACKF2(e0, e1, r5); t5 = fmaxf(e0, e1);                             \
        UNPACKF2(e0, e1, r6); t6 = fmaxf(e0, e1);                             \
        UNPACKF2(e0, e1, r7); t7 = fmaxf(e0, e1);                             \
        float u0 = fmaxf(t0, t1), u1 = fmaxf(t2, t3);                         \
        float u2 = fmaxf(t4, t5), u3 = fmaxf(t6, t7);                         \
        s = fmaxf(fmaxf(fmaxf(u0, u1), fmaxf(u2, u3)), q16);                  \
    }

#define RF(j)                                                                 \
    {                                                                         \
        U0[j] = pf0[(j) * CHUNKS]; U1[j] = pf1[(j) * CHUNKS];                 \
        U2[j] = pf2[(j) * CHUNKS]; U3[j] = pf3[(j) * CHUNKS];                 \
    }

#define ADVANCE()                                                             \
    {                                                                         \
        fk += PD;                                                             \
        if (fk == CW) {                                                       \
            fk = 0; ++fq;                                                     \
            pf0 = b0 + fq; pf1 = b1 + fq; pf2 = b2 + fq;                      \
            pf3 = b3 + fq; pf4 = b4 + fq;                                     \
        } else {                                                              \
            pf0 += PD * CHUNKS; pf1 += PD * CHUNKS;                           \
            pf2 += PD * CHUNKS; pf3 += PD * CHUNKS;                           \
            pf4 += 2 * CHUNKS;                                                \
        }                                                                     \
    }

// Invariant entering each BLOCK8: pf* point at the NEXT block; CCa/CCb hold
// the CURRENT block's plane-16 pair (fetched a full block early).
#define BLOCK8()                                                              \
    {                                                                         \
        float4 CAn = pf4[0];                                                  \
        float4 CBn = pf4[CHUNKS];                                             \
        STEP(0, CCa.x); RF(0); STEP(1, CCa.y); RF(1);                         \
        STEP(2, CCa.z); RF(2); STEP(3, CCa.w); RF(3);                         \
        STEP(4, CCb.x); RF(4); STEP(5, CCb.y); RF(5);                         \
        STEP(6, CCb.z); RF(6); STEP(7, CCb.w); RF(7);                         \
        CCa = CAn; CCb = CBn;                                                 \
        ADVANCE();                                                            \
    }

#define BLOCK8_ST(en, it)                                                     \
    {                                                                         \
        float4 CAn = pf4[0];                                                  \
        float4 CBn = pf4[CHUNKS];                                             \
        float ss0 = s; STEP(0, CCa.x); RF(0);                                 \
        float ss1 = s; STEP(1, CCa.y); RF(1);                                 \
        float ss2 = s; STEP(2, CCa.z); RF(2);                                 \
        float ss3 = s; STEP(3, CCa.w); RF(3);                                 \
        float ss4 = s; STEP(4, CCb.x); RF(4);                                 \
        float ss5 = s; STEP(5, CCb.y); RF(5);                                 \
        float ss6 = s; STEP(6, CCb.z); RF(6);                                 \
        float ss7 = s; STEP(7, CCb.w); RF(7);                                 \
        CCa = CAn; CCb = CBn;                                                 \
        ADVANCE();                                                            \
        float4* e4 = (float4*)((en) + (it) * PD);                             \
        e4[0] = make_float4(ss0, ss1, ss2, ss3);                              \
        e4[1] = make_float4(ss4, ss5, ss6, ss7);                              \
    }

__global__ void __launch_bounds__(32) k_scan(const float* __restrict__ x) {
    int gid = blockIdx.x * 32 + threadIdx.x;   // 0..2559
    int row = gid / CHUNKS;
    int c   = gid % CHUNKS;
    int start_w = c * CW;
    int warm_w  = max(0, start_w - WARM_W);    // NOT CW-aligned; %8==0 always

    const ulonglong2* b0 = (const ulonglong2*)(g_p0 + row * TWPR);
    const ulonglong2* b1 = (const ulonglong2*)(g_p1 + row * TWPR);
    const ulonglong2* b2 = (const ulonglong2*)(g_p2 + row * TWPR);
    const ulonglong2* b3 = (const ulonglong2*)(g_p3 + row * TWPR);
    const float4*     b4 = (const float4*)g_p4 + row * (TWPR / 4);

    int fq = warm_w / CW;
    int fk = warm_w % CW;                      // 0 (clamped) or 88
    const ulonglong2* pf0 = b0 + fk * CHUNKS + fq;
    const ulonglong2* pf1 = b1 + fk * CHUNKS + fq;
    const ulonglong2* pf2 = b2 + fk * CHUNKS + fq;
    const ulonglong2* pf3 = b3 + fk * CHUNKS + fq;
    const float4*     pf4 = b4 + (fk >> 2) * CHUNKS + fq;

    unsigned long long K01, K23, K45, K67, K89, KAB, KCD, KEF;
    PACKF2(K01, SC(0),  SC(1));  PACKF2(K23, SC(2),  SC(3));
    PACKF2(K45, SC(4),  SC(5));  PACKF2(K67, SC(6),  SC(7));
    PACKF2(K89, SC(8),  SC(9));  PACKF2(KAB, SC(10), SC(11));
    PACKF2(KCD, SC(12), SC(13)); PACKF2(KEF, SC(14), SC(15));

    ulonglong2 U0[PD], U1[PD], U2[PD], U3[PD];
#pragma unroll
    for (int j = 0; j < PD; ++j) RF(j);
    float4 CCa = pf4[0];
    float4 CCb = pf4[CHUNKS];

    float s;
    if (warm_w == 0) {
        // exact init: reference seeds with rect_db[row][0]
        s = C_DB * __log2f(fabsf(x[row * N_SAMP]) + 1e-8f);
    } else {
        // seed: fixed point of all-attack plane, biased 25 dB low so
        // recovery runs at the fast attack rate
        const float SEST = (float)(1.0 / (1.0 - slope16(16)));
        s = fmaf(CCa.x, SEST, -25.0f);
    }

    ADVANCE();   // pf* now point at the next block

    // ---- warmup (no stores); per-lane trip count, divergence OK ----
    int nwb = (start_w - warm_w) >> 3;
    for (int i = 0; i < nwb; ++i) BLOCK8();

    // ---- active: CW/PD = 22 blocks, store entry states ----
    float* en = g_entry + row * EPR + start_w;
    for (int i = 0; i < CW / PD; ++i) BLOCK8_ST(en, i);
}

// ---------------- kernel 3: expand + LUT epilogue -------------------------
__global__ void __launch_bounds__(256) k_expand(const float* __restrict__ x,
                                                const float* __restrict__ thr,
                                                const float* __restrict__ dep,
                                                float* __restrict__ out) {
    int wi = blockIdx.x * 256 + threadIdx.x;
    if (wi >= WPR16) return;
    int row = blockIdx.y;

    float tdb = fmaf(thr[row], 40.0f, -40.0f);
    float dpv = dep[row];
    bool  d1  = (dpv == 1.0f);
    float off = (-tdb - LUT_LO_F) * LUT_INVSTEP_F;

    const float AT = (float)A_AT_D, RL = (float)A_REL_D;
    const float BT = 1.0f - AT, BR = 1.0f - RL;

    float s = g_entry[row * EPR + wi];

    const float* xr = x + row * N_SAMP;
    float* outr = out + row * N_SAMP;
    int base = wi * 16;
    int nval = (wi < FULLW) ? 16 : (N_SAMP - base);

    float xi[16];
    if (nval == 16) {
        const float4* x4 = (const float4*)(xr + base);
        float4 a = x4[0], b = x4[1], c = x4[2], d = x4[3];
        xi[0]=a.x; xi[1]=a.y; xi[2]=a.z; xi[3]=a.w;
        xi[4]=b.x; xi[5]=b.y; xi[6]=b.z; xi[7]=b.w;
        xi[8]=c.x; xi[9]=c.y; xi[10]=c.z; xi[11]=c.w;
        xi[12]=d.x; xi[13]=d.y; xi[14]=d.z; xi[15]=d.w;
    } else {
#pragma unroll
        for (int i = 0; i < 16; ++i)
            xi[i] = (i < nval) ? xr[base + i] : 0.0f;
    }

    float o[16];
#pragma unroll
    for (int i = 0; i < 16; ++i) {
        float v = C_DB * __log2f(fabsf(xi[i]) + 1e-8f);
        s = fmaxf(fmaf(AT, s, BT * v), fmaf(RL, s, BR * v));

        float fi = fmaf(s, LUT_INVSTEP_F, off);
        fi = fminf(fmaxf(fi, 0.0f), (float)(LUT_N - 2) + 0.999f);
        int   ii = (int)fi;
        float fr = fi - (float)ii;
        float2 e = g_lut[ii];
        float m = fmaf(fr, e.y, e.x);
        if (!d1) m = exp2f(__log2f(m) * dpv);
        o[i] = xi[i] * m;
    }

    if (nval == 16) {
        float4* o4 = (float4*)(outr + base);
        o4[0] = make_float4(o[0],  o[1],  o[2],  o[3]);
        o4[1] = make_float4(o[4],  o[5],  o[6],  o[7]);
        o4[2] = make_float4(o[8],  o[9],  o[10], o[11]);
        o4[3] = make_float4(o[12], o[13], o[14], o[15]);
    } else {
#pragma unroll
        for (int i = 0; i < 16; ++i)
            if (i < nval) outr[base + i] = o[i];
    }
}

// ---------------- entry point (single stream, no allocations) -------------
extern "C" void kernel_launch(void* const* d_in, const int* in_sizes, int n_in,
                              void* d_out, int out_size) {
    const float* x   = (const float*)d_in[0];
    const float* thr = (const float*)d_in[1];
    const float* dep = (const float*)d_in[2];
    float* out = (float*)d_out;

    k_prepass<<<dim3(CW, ROWS), CHUNKS>>>(x);
    k_scan<<<(ROWS * CHUNKS) / 32, 32>>>(x);
    k_expand<<<dim3((WPR16 + 255) / 256, ROWS), 256>>>(x, thr, dep, out);
}